// round 7
// baseline (speedup 1.0000x reference)
#include <cuda_runtime.h>
#include <cstdint>

// ROI adaptive average pooling: one WARP per (b, s, channel-group-of-4),
// single pass over roi rows, 2 channels packed per LDG.64.
//
// x:    [B=8, C=64, H=256, W=256] fp32
// rois: [B=8, S=128, 5] int32 (idx, x1, y1, x2, y2); sides in [8,40]
// out:  [B, S*C, 7, 7] fp32; torch adaptive-pool integer bin bounds.
//
// Lane mapping: half = lane>>4 selects channel within a pair, k = lane&15
// selects an aligned float2 covering crop-window cols 2k,2k+1 (window starts
// at x1 & ~1; the off = x1&1 junk column is skipped by phase 2).
// Set A = channels c0+half, set B = channels c0+2+half.
//
// Band straddle rows (torch ceil bound) are handled at the rare warp-uniform
// band-transition branch by RE-LOADING the boundary row (L1 hit) -- the hot
// per-row body is pure load+add.

namespace {
constexpr int B  = 8;
constexpr int C  = 64;
constexpr int H  = 256;
constexpr int W  = 256;
constexpr int S  = 128;
constexpr int OH = 7;
constexpr int OW = 7;
constexpr int CH = H * W;        // floats per channel
constexpr int W2 = W / 2;        // row stride in float2
constexpr int PITCH = 42;        // smem cols (aligned window width)

constexpr int NCH = 4;
constexpr int WPB = 8;
constexpr int THREADS = WPB * 32;
constexpr int NTASK = B * S * (C / NCH);  // 16384
constexpr int NBLOCK = NTASK / WPB;       // 2048
}

__global__ void __launch_bounds__(THREADS) roi_pool_pack2_kernel(
    const float* __restrict__ x,
    const int*   __restrict__ rois,
    float*       __restrict__ out)
{
    __shared__ float cs_all[WPB][NCH][OH][PITCH];   // 8*4*7*42*4 = 37632 B

    const int lane = threadIdx.x & 31;
    const int warp = threadIdx.x >> 5;

    const int task = blockIdx.x * WPB + warp;
    const int cg   = task & (C / NCH - 1);
    const int bs   = task >> 4;              // b*S + s
    const int b    = bs >> 7;
    const int c0   = cg * NCH;

    const int* r = rois + bs * 5;
    const int x1 = r[1];
    const int y1 = r[2];
    const int w  = r[3] - x1;                // [8,40]
    const int h  = r[4] - y1;                // [8,40]

    const int off = x1 & 1;
    const int x1a = x1 - off;

    const int half = lane >> 4;              // channel within pair
    const int k    = lane & 15;              // float2 slot: cols 2k, 2k+1

    // pA: channel c0+half, float2 at window col 2k, row y1.
    const float2* pA = reinterpret_cast<const float2*>(
        x + (size_t)(b * C + c0 + half) * CH + (size_t)y1 * W + x1a) + k;
    // +2 channels = 2*CH floats = CH float2
    const float2* pB = pA + CH;

    float (*cs)[OH][PITCH] = cs_all[warp];

    if (off + w <= 32) {
        // ---------------- narrow: main lanes only, unroll 4 ----------------
        float2 aA = make_float2(0.f, 0.f);
        float2 aB = make_float2(0.f, 0.f);
        int cur = 0;
        int eyc = (h + 6) / 7;               // ceil((cur+1)h/7)
        int syn = h / 7;                     // floor((cur+1)h/7)

        for (int r0 = 0; r0 < h; r0 += 4) {
            float2 vA[4], vB[4];
            #pragma unroll
            for (int i = 0; i < 4; ++i) {
                const int rc = min(r0 + i, h - 1);
                vA[i] = __ldg(pA + (size_t)rc * W2);
                vB[i] = __ldg(pB + (size_t)rc * W2);
            }
            #pragma unroll
            for (int i = 0; i < 4; ++i) {
                const int rr = r0 + i;
                if (rr < h) {                            // warp-uniform
                    if (rr == eyc) {                     // band transition
                        *reinterpret_cast<float2*>(&cs[half][cur][2 * k])     = aA;
                        *reinterpret_cast<float2*>(&cs[2 + half][cur][2 * k]) = aB;
                        if (eyc > syn) {                 // straddle: reseed from row syn
                            aA = __ldg(pA + (size_t)syn * W2);
                            aB = __ldg(pB + (size_t)syn * W2);
                        } else {
                            aA = make_float2(0.f, 0.f);
                            aB = make_float2(0.f, 0.f);
                        }
                        ++cur;
                        eyc = ((cur + 1) * h + 6) / 7;
                        syn = ((cur + 1) * h) / 7;
                    }
                    aA.x += vA[i].x; aA.y += vA[i].y;
                    aB.x += vB[i].x; aB.y += vB[i].y;
                }
            }
        }
        *reinterpret_cast<float2*>(&cs[half][6][2 * k])     = aA;
        *reinterpret_cast<float2*>(&cs[2 + half][6][2 * k]) = aB;
    } else {
        // ------- wide (off+w in 33..42): main + ext (cols 32..41), unroll 2 -------
        const bool ext = (k < 5);
        const float2 z2 = make_float2(0.f, 0.f);
        float2 aA = z2, aB = z2, eA = z2, eB = z2;
        int cur = 0;
        int eyc = (h + 6) / 7;
        int syn = h / 7;

        for (int r0 = 0; r0 < h; r0 += 2) {
            float2 vA[2], vB[2], wA[2], wB[2];
            #pragma unroll
            for (int i = 0; i < 2; ++i) {
                const int rc = min(r0 + i, h - 1);
                vA[i] = __ldg(pA + (size_t)rc * W2);
                vB[i] = __ldg(pB + (size_t)rc * W2);
                wA[i] = ext ? __ldg(pA + (size_t)rc * W2 + 16) : z2;
                wB[i] = ext ? __ldg(pB + (size_t)rc * W2 + 16) : z2;
            }
            #pragma unroll
            for (int i = 0; i < 2; ++i) {
                const int rr = r0 + i;
                if (rr < h) {
                    if (rr == eyc) {
                        *reinterpret_cast<float2*>(&cs[half][cur][2 * k])     = aA;
                        *reinterpret_cast<float2*>(&cs[2 + half][cur][2 * k]) = aB;
                        if (ext) {
                            *reinterpret_cast<float2*>(&cs[half][cur][32 + 2 * k])     = eA;
                            *reinterpret_cast<float2*>(&cs[2 + half][cur][32 + 2 * k]) = eB;
                        }
                        if (eyc > syn) {
                            aA = __ldg(pA + (size_t)syn * W2);
                            aB = __ldg(pB + (size_t)syn * W2);
                            eA = ext ? __ldg(pA + (size_t)syn * W2 + 16) : z2;
                            eB = ext ? __ldg(pB + (size_t)syn * W2 + 16) : z2;
                        } else {
                            aA = z2; aB = z2; eA = z2; eB = z2;
                        }
                        ++cur;
                        eyc = ((cur + 1) * h + 6) / 7;
                        syn = ((cur + 1) * h) / 7;
                    }
                    aA.x += vA[i].x; aA.y += vA[i].y;
                    aB.x += vB[i].x; aB.y += vB[i].y;
                    eA.x += wA[i].x; eA.y += wA[i].y;
                    eB.x += wB[i].x; eB.y += wB[i].y;
                }
            }
        }
        *reinterpret_cast<float2*>(&cs[half][6][2 * k])     = aA;
        *reinterpret_cast<float2*>(&cs[2 + half][6][2 * k]) = aB;
        if (ext) {
            *reinterpret_cast<float2*>(&cs[half][6][32 + 2 * k])     = eA;
            *reinterpret_cast<float2*>(&cs[2 + half][6][32 + 2 * k]) = eB;
        }
    }
    __syncwarp();

    // ---- phase 2: bins from column sums (crop col j at smem index off+j) ----
    float* obase = out + (size_t)(bs * C + c0) * (OH * OW);
    for (int t = lane; t < OH * OW; t += 32) {
        const int oy = t / OW;
        const int ox = t - oy * OW;

        const int sx = (ox * w) / OW;
        const int ex = ((ox + 1) * w + (OW - 1)) / OW;
        const int sy = (oy * h) / OH;
        const int ey = ((oy + 1) * h + (OH - 1)) / OH;

        float q0 = 0.f, q1 = 0.f, q2 = 0.f, q3 = 0.f;
        #pragma unroll 4
        for (int xx = off + sx; xx < off + ex; ++xx) {
            q0 += cs[0][oy][xx];
            q1 += cs[1][oy][xx];
            q2 += cs[2][oy][xx];
            q3 += cs[3][oy][xx];
        }

        const float inv = 1.0f / (float)((ey - sy) * (ex - sx));
        obase[t]               = q0 * inv;
        obase[t +     OH * OW] = q1 * inv;
        obase[t + 2 * OH * OW] = q2 * inv;
        obase[t + 3 * OH * OW] = q3 * inv;
    }
}

extern "C" void kernel_launch(void* const* d_in, const int* in_sizes, int n_in,
                              void* d_out, int out_size)
{
    const float* x    = (const float*)d_in[0];
    const int*   rois = (const int*)d_in[1];
    float*       out  = (float*)d_out;

    roi_pool_pack2_kernel<<<NBLOCK, THREADS>>>(x, rois, out);
}

// round 8
// speedup vs baseline: 1.0730x; 1.0730x over previous
#include <cuda_runtime.h>
#include <cstdint>

// ROI adaptive average pooling: one WARP per (b, s, channel-group-of-4),
// single pass over roi rows with incremental band tracking.
// R8 = R5 structure (16 scalar LDGs in flight per unroll group) with:
//   - straddle handled by re-loading the boundary row at the (rare) band
//     transition (L1 hit) instead of per-row select-carry registers
//   - __launch_bounds__(256, 6) to force <=40 regs -> 6 blocks/SM
//
// x:    [B=8, C=64, H=256, W=256] fp32
// rois: [B=8, S=128, 5] int32 (idx, x1, y1, x2, y2); sides in [8,40]
// out:  [B, S*C, 7, 7] fp32; torch adaptive-pool integer bin bounds.

namespace {
constexpr int B  = 8;
constexpr int C  = 64;
constexpr int H  = 256;
constexpr int W  = 256;
constexpr int S  = 128;
constexpr int OH = 7;
constexpr int OW = 7;
constexpr int MAXD = 40;
constexpr int CH = H * W;

constexpr int NCH = 4;                    // channels per warp
constexpr int WPB = 8;                    // warps per block
constexpr int THREADS = WPB * 32;
constexpr int NTASK = B * S * (C / NCH);  // 16384
constexpr int NBLOCK = NTASK / WPB;       // 2048
}

__global__ void __launch_bounds__(THREADS, 6) roi_pool_scan6_kernel(
    const float* __restrict__ x,
    const int*   __restrict__ rois,
    float*       __restrict__ out)
{
    __shared__ float cs_all[WPB][NCH][OH][MAXD];   // 8*4*7*40*4 = 35840 B

    const int lane = threadIdx.x & 31;
    const int warp = threadIdx.x >> 5;

    const int task = blockIdx.x * WPB + warp;
    const int cg   = task & (C / NCH - 1);
    const int bs   = task >> 4;
    const int b    = bs >> 7;
    const int c0   = cg * NCH;

    const int* r = rois + bs * 5;
    const int x1 = r[1];
    const int y1 = r[2];
    const int w  = r[3] - x1;              // [8,40]
    const int h  = r[4] - y1;              // [8,40]

    const float* p0 = x + (size_t)(b * C + c0) * CH + (size_t)y1 * W + x1;

    float (*cs)[OH][MAXD] = cs_all[warp];

    if (w <= 32) {
        // ---------------- narrow path: one lane-set, unroll 4 ----------------
        const bool act = (lane < w);
        float a0 = 0.f, a1 = 0.f, a2 = 0.f, a3 = 0.f;
        int cur = 0;
        int eyc = (h + 6) / 7;                               // ceil((cur+1)h/7)
        int syn = h / 7;                                     // floor((cur+1)h/7)

        for (int r0 = 0; r0 < h; r0 += 4) {
            float v[4][NCH];
            #pragma unroll
            for (int i = 0; i < 4; ++i) {
                const float* p = p0 + (size_t)(r0 + i) * W + lane;
                const bool pv = act && (r0 + i < h);
                v[i][0] = pv ? __ldg(p)          : 0.f;
                v[i][1] = pv ? __ldg(p + CH)     : 0.f;
                v[i][2] = pv ? __ldg(p + 2 * CH) : 0.f;
                v[i][3] = pv ? __ldg(p + 3 * CH) : 0.f;
            }
            #pragma unroll
            for (int i = 0; i < 4; ++i) {
                const int rr = r0 + i;
                if (rr < h) {                                // warp-uniform
                    if (rr == eyc) {                         // band transition (rare)
                        if (act) {
                            cs[0][cur][lane] = a0;
                            cs[1][cur][lane] = a1;
                            cs[2][cur][lane] = a2;
                            cs[3][cur][lane] = a3;
                        }
                        if (eyc > syn) {                     // straddle: reseed from row syn (L1 hit)
                            const float* ps = p0 + (size_t)syn * W + lane;
                            a0 = act ? __ldg(ps)          : 0.f;
                            a1 = act ? __ldg(ps + CH)     : 0.f;
                            a2 = act ? __ldg(ps + 2 * CH) : 0.f;
                            a3 = act ? __ldg(ps + 3 * CH) : 0.f;
                        } else {
                            a0 = 0.f; a1 = 0.f; a2 = 0.f; a3 = 0.f;
                        }
                        ++cur;
                        eyc = ((cur + 1) * h + 6) / 7;
                        syn = ((cur + 1) * h) / 7;
                    }
                    a0 += v[i][0];
                    a1 += v[i][1];
                    a2 += v[i][2];
                    a3 += v[i][3];
                }
            }
        }
        if (act) {                                           // cur == 6 here
            cs[0][cur][lane] = a0;
            cs[1][cur][lane] = a1;
            cs[2][cur][lane] = a2;
            cs[3][cur][lane] = a3;
        }
    } else {
        // ---------------- wide path (w in 33..40): two lane-sets, unroll 2 ----------------
        const bool act1 = (lane + 32 < w);
        float a0 = 0.f, a1 = 0.f, a2 = 0.f, a3 = 0.f;
        float b0 = 0.f, b1 = 0.f, b2 = 0.f, b3 = 0.f;
        int cur = 0;
        int eyc = (h + 6) / 7;
        int syn = h / 7;

        for (int r0 = 0; r0 < h; r0 += 2) {
            float va[2][NCH], vb[2][NCH];
            #pragma unroll
            for (int i = 0; i < 2; ++i) {
                const float* p = p0 + (size_t)(r0 + i) * W + lane;
                const bool pv  = (r0 + i < h);
                const bool pv1 = pv && act1;
                va[i][0] = pv  ? __ldg(p)               : 0.f;
                va[i][1] = pv  ? __ldg(p + CH)          : 0.f;
                va[i][2] = pv  ? __ldg(p + 2 * CH)      : 0.f;
                va[i][3] = pv  ? __ldg(p + 3 * CH)      : 0.f;
                vb[i][0] = pv1 ? __ldg(p + 32)          : 0.f;
                vb[i][1] = pv1 ? __ldg(p + CH + 32)     : 0.f;
                vb[i][2] = pv1 ? __ldg(p + 2 * CH + 32) : 0.f;
                vb[i][3] = pv1 ? __ldg(p + 3 * CH + 32) : 0.f;
            }
            #pragma unroll
            for (int i = 0; i < 2; ++i) {
                const int rr = r0 + i;
                if (rr < h) {
                    if (rr == eyc) {
                        cs[0][cur][lane] = a0;
                        cs[1][cur][lane] = a1;
                        cs[2][cur][lane] = a2;
                        cs[3][cur][lane] = a3;
                        if (act1) {
                            cs[0][cur][lane + 32] = b0;
                            cs[1][cur][lane + 32] = b1;
                            cs[2][cur][lane + 32] = b2;
                            cs[3][cur][lane + 32] = b3;
                        }
                        if (eyc > syn) {                     // reseed from row syn (L1 hit)
                            const float* ps = p0 + (size_t)syn * W + lane;
                            a0 = __ldg(ps);
                            a1 = __ldg(ps + CH);
                            a2 = __ldg(ps + 2 * CH);
                            a3 = __ldg(ps + 3 * CH);
                            b0 = act1 ? __ldg(ps + 32)          : 0.f;
                            b1 = act1 ? __ldg(ps + CH + 32)     : 0.f;
                            b2 = act1 ? __ldg(ps + 2 * CH + 32) : 0.f;
                            b3 = act1 ? __ldg(ps + 3 * CH + 32) : 0.f;
                        } else {
                            a0 = 0.f; a1 = 0.f; a2 = 0.f; a3 = 0.f;
                            b0 = 0.f; b1 = 0.f; b2 = 0.f; b3 = 0.f;
                        }
                        ++cur;
                        eyc = ((cur + 1) * h + 6) / 7;
                        syn = ((cur + 1) * h) / 7;
                    }
                    a0 += va[i][0]; a1 += va[i][1]; a2 += va[i][2]; a3 += va[i][3];
                    b0 += vb[i][0]; b1 += vb[i][1]; b2 += vb[i][2]; b3 += vb[i][3];
                }
            }
        }
        cs[0][cur][lane] = a0;
        cs[1][cur][lane] = a1;
        cs[2][cur][lane] = a2;
        cs[3][cur][lane] = a3;
        if (act1) {
            cs[0][cur][lane + 32] = b0;
            cs[1][cur][lane + 32] = b1;
            cs[2][cur][lane + 32] = b2;
            cs[3][cur][lane + 32] = b3;
        }
    }
    __syncwarp();

    // ---- phase 2: bins from column sums, 4 channels per lane-task ----
    float* obase = out + (size_t)(bs * C + c0) * (OH * OW);
    for (int t = lane; t < OH * OW; t += 32) {
        const int oy = t / OW;
        const int ox = t - oy * OW;

        const int sx = (ox * w) / OW;
        const int ex = ((ox + 1) * w + (OW - 1)) / OW;
        const int sy = (oy * h) / OH;
        const int ey = ((oy + 1) * h + (OH - 1)) / OH;

        float q0 = 0.f, q1 = 0.f, q2 = 0.f, q3 = 0.f;
        #pragma unroll 4
        for (int xx = sx; xx < ex; ++xx) {
            q0 += cs[0][oy][xx];
            q1 += cs[1][oy][xx];
            q2 += cs[2][oy][xx];
            q3 += cs[3][oy][xx];
        }

        const float inv = 1.0f / (float)((ey - sy) * (ex - sx));
        obase[t]               = q0 * inv;
        obase[t +     OH * OW] = q1 * inv;
        obase[t + 2 * OH * OW] = q2 * inv;
        obase[t + 3 * OH * OW] = q3 * inv;
    }
}

extern "C" void kernel_launch(void* const* d_in, const int* in_sizes, int n_in,
                              void* d_out, int out_size)
{
    const float* x    = (const float*)d_in[0];
    const int*   rois = (const int*)d_in[1];
    float*       out  = (float*)d_out;

    roi_pool_scan6_kernel<<<NBLOCK, THREADS>>>(x, rois, out);
}